// round 8
// baseline (speedup 1.0000x reference)
#include <cuda_runtime.h>
#include <math.h>

#define B_   256
#define C_   512
#define L_   2048
#define HID  32
#define FL   8

// Scratch (no allocations). Counters self-reset each run -> graph-replay safe.
__device__ float g_stat[B_ * C_];   // row maxes (scalar access only)
__device__ float g_loss[B_];        // per-sample ortho loss
__device__ int   g_samp_cnt[B_];    // blocks completed per sample (0..64)
__device__ int   g_done_cnt;        // samples completed (0..256)

// ---------------------------------------------------------------------------
// Single fused kernel, R2 shape: 16384 blocks x 256 threads, 110 waves.
// Each warp max-reduces one row (2048 floats, float4). After syncthreads,
// warps 1..7 exit immediately; warp 0 alone does: fence + sample counter.
// The 64th block of a sample runs that sample's MLP + loss on warp 0 (no
// shared memory, cross-lane via shfl). The 256th sample-completer reduces.
// ---------------------------------------------------------------------------
__global__ void __launch_bounds__(256) dywan_fused_kernel(
    const float* __restrict__ x,
    const float* __restrict__ W1, const float* __restrict__ b1,
    const float* __restrict__ W2, const float* __restrict__ b2,
    const float* __restrict__ W3, const float* __restrict__ b3,
    float* __restrict__ out)
{
    const int warp = threadIdx.x >> 5;
    const int lane = threadIdx.x & 31;
    const int row  = blockIdx.x * 8 + warp;
    const int b    = blockIdx.x >> 6;          // 64 blocks per sample

    // ---- Phase 1: row max (HBM-bound, identical to the 91.8%-DRAM R2 path) ----
    const float4* p = reinterpret_cast<const float4*>(x + (size_t)row * L_);
    float m = -INFINITY;
#pragma unroll
    for (int i = 0; i < 16; ++i) {
        float4 v = p[lane + 32 * i];
        m = fmaxf(m, fmaxf(fmaxf(v.x, v.y), fmaxf(v.z, v.w)));
    }
#pragma unroll
    for (int o = 16; o > 0; o >>= 1)
        m = fmaxf(m, __shfl_xor_sync(0xFFFFFFFFu, m, o));
    if (lane == 0) g_stat[row] = m;

    __syncthreads();               // block's 8 stats globally issued (program order)
    if (warp != 0) return;         // 7/8 warps exit with zero epilogue cost

    // ---- Warp-0-only epilogue: one fence + one atomic per block ----
    __threadfence();               // release this block's 8 stat writes
    int old = 0;
    if (lane == 0) old = atomicAdd(&g_samp_cnt[b], 1);
    old = __shfl_sync(0xFFFFFFFFu, old, 0);
    if (old != 63) return;         // not the sample's last block

    if (lane == 0) g_samp_cnt[b] = 0;   // self-reset (no other block touches it now)
    __threadfence();               // acquire: stats from all 64 blocks now visible

    // ---- Phase 2: warp-serial MLP for sample b (registers + shfl only) ----
    const int t = lane;            // 0..31, one MLP unit per lane
    const float* sp = g_stat + (size_t)b * C_;

    // Layer 1: h1[t] = relu(W1[t,:] . stat + b1[t]), 4 accumulator chains
    float h1v;
    {
        const float* w = W1 + (size_t)t * C_;
        float a0 = b1[t], a1 = 0.f, a2 = 0.f, a3 = 0.f;
#pragma unroll 4
        for (int c = 0; c < C_; c += 4) {
            a0 = fmaf(w[c + 0], sp[c + 0], a0);   // sp loads are warp-broadcast
            a1 = fmaf(w[c + 1], sp[c + 1], a1);
            a2 = fmaf(w[c + 2], sp[c + 2], a2);
            a3 = fmaf(w[c + 3], sp[c + 3], a3);
        }
        h1v = fmaxf((a0 + a1) + (a2 + a3), 0.0f);
    }

    // Layer 2: h2[t] = relu(W2[t,:] . h1 + b2[t]); h1 gathered via shfl
    float h2v;
    {
        float a = b2[t];
        const float* w = W2 + t * HID;
#pragma unroll
        for (int k = 0; k < HID; ++k)
            a = fmaf(w[k], __shfl_sync(0xFFFFFFFFu, h1v, k), a);
        h2v = fmaxf(a, 0.0f);
    }

    // Layer 3: f[t] = W3[t,:] . h2 + b3[t] for t < 16
    float fv = 0.0f;
    {
        float a = (t < 2 * FL) ? b3[t] : 0.0f;
        const float* w = W3 + (t < 2 * FL ? t : 0) * HID;
#pragma unroll
        for (int k = 0; k < HID; ++k)
            a = fmaf(w[k], __shfl_sync(0xFFFFFFFFu, h2v, k), a);
        fv = a;
    }
    if (t < FL)               out[(size_t)b * FL + t] = fv;                          // lo
    else if (t < 2 * FL)      out[(size_t)B_ * FL + (size_t)b * FL + (t - FL)] = fv; // hi

    // ---- Per-sample ortho loss on lane 0 (gather 16 filter values via shfl) ----
    float fbuf[2 * FL];
#pragma unroll
    for (int i = 0; i < 2 * FL; ++i)
        fbuf[i] = __shfl_sync(0xFFFFFFFFu, fv, i);

    if (lane == 0) {
        float lo[FL], hi[FL];
        float nl = 0.0f, nh = 0.0f;
#pragma unroll
        for (int i = 0; i < FL; ++i) {
            lo[i] = fbuf[i]; hi[i] = fbuf[FL + i];
            nl += lo[i] * lo[i];
            nh += hi[i] * hi[i];
        }
        const float il = 1.0f / sqrtf(nl);
        const float ih = 1.0f / sqrtf(nh);
        float Ln[FL], Hn[FL];
#pragma unroll
        for (int i = 0; i < FL; ++i) { Ln[i] = lo[i] * il; Hn[i] = hi[i] * ih; }

        float acc = 0.0f;
#pragma unroll
        for (int sft = 1; sft < FL; sft += 2) {   // shifts 1,3,5,7
            float d = 0.0f;
#pragma unroll
            for (int i = 0; i < FL; ++i) d += Ln[i] * Ln[(i - sft + FL) & (FL - 1)];
            acc += fabsf(d);
        }
        float dlh = 0.0f, dll = 0.0f, dhh = 0.0f;
#pragma unroll
        for (int i = 0; i < FL; ++i) {
            dlh += Ln[i] * Hn[i];
            dll += Ln[i] * Ln[i];
            dhh += Hn[i] * Hn[i];
        }
        acc += fabsf(dlh) + fabsf(dll - 1.0f) + fabsf(dhh - 1.0f);
        g_loss[b] = acc;
    }

    // ---- Phase 3: last sample overall reduces the 256 losses ----
    __threadfence();               // release g_loss[b]
    int old2 = 0;
    if (lane == 0) old2 = atomicAdd(&g_done_cnt, 1);
    old2 = __shfl_sync(0xFFFFFFFFu, old2, 0);
    if (old2 != B_ - 1) return;

    if (lane == 0) g_done_cnt = 0; // self-reset for graph replay
    __threadfence();               // acquire all g_loss writes

    // deterministic: fixed per-lane serial sum then fixed shuffle tree
    float a = 0.0f;
#pragma unroll
    for (int i = 0; i < 8; ++i) a += g_loss[lane * 8 + i];
#pragma unroll
    for (int o = 16; o > 0; o >>= 1)
        a += __shfl_xor_sync(0xFFFFFFFFu, a, o);
    if (lane == 0) out[2 * B_ * FL] = a * (1.0f / (float)B_);
}

// ---------------------------------------------------------------------------
extern "C" void kernel_launch(void* const* d_in, const int* in_sizes, int n_in,
                              void* d_out, int out_size)
{
    const float* x  = (const float*)d_in[0];
    const float* W1 = (const float*)d_in[1];
    const float* b1 = (const float*)d_in[2];
    const float* W2 = (const float*)d_in[3];
    const float* b2 = (const float*)d_in[4];
    const float* W3 = (const float*)d_in[5];
    const float* b3 = (const float*)d_in[6];
    float* out = (float*)d_out;

    dywan_fused_kernel<<<(B_ * C_) / 8, 256>>>(x, W1, b1, W2, b2, W3, b3, out);
}

// round 12
// speedup vs baseline: 2.4825x; 2.4825x over previous
#include <cuda_runtime.h>
#include <math.h>

#define B_   256
#define C_   512
#define L_   2048
#define HID  32
#define FL   8

// Scratch (no allocations). Counter self-resets -> graph-replay safe.
__device__ float g_stat[B_ * C_];   // row maxes
__device__ float g_loss[B_];        // per-sample ortho loss
__device__ int   g_done_cnt;        // blocks of kernel B completed (0..256)

// ---------------------------------------------------------------------------
// Kernel A: stat[b,c] = max over L (proven R2 shape: 91.8% DRAM, 148 us).
// NO fences, NO barriers, NO atomics — pure streaming.
// ---------------------------------------------------------------------------
__global__ void __launch_bounds__(256) dywan_max_kernel(
    const float* __restrict__ x, float* __restrict__ stat)
{
    const int warp = threadIdx.x >> 5;
    const int lane = threadIdx.x & 31;
    const int row  = blockIdx.x * 8 + warp;

    const float4* p = reinterpret_cast<const float4*>(x + (size_t)row * L_);
    float m = -INFINITY;
#pragma unroll
    for (int i = 0; i < 16; ++i) {
        float4 v = p[lane + 32 * i];
        m = fmaxf(m, fmaxf(fmaxf(v.x, v.y), fmaxf(v.z, v.w)));
    }
#pragma unroll
    for (int o = 16; o > 0; o >>= 1)
        m = fmaxf(m, __shfl_xor_sync(0xFFFFFFFFu, m, o));
    if (lane == 0) stat[row] = m;
}

// ---------------------------------------------------------------------------
// Kernel B: MLP + per-sample loss + fused final reduction.
// 256 blocks x 256 threads. Layer 1 parallelized over 8 warps (4 rows each,
// lane-coalesced W1 loads). Only 256 fence/atomic pairs total -> negligible.
// ---------------------------------------------------------------------------
__global__ void __launch_bounds__(256) dywan_mlp_kernel(
    const float* __restrict__ stat,
    const float* __restrict__ W1, const float* __restrict__ b1,
    const float* __restrict__ W2, const float* __restrict__ b2,
    const float* __restrict__ W3, const float* __restrict__ b3,
    float* __restrict__ out, float* __restrict__ loss)
{
    __shared__ float s[C_];
    __shared__ float h1[HID];
    __shared__ float h2[HID];
    __shared__ float f[2 * FL];
    __shared__ int   s_final;

    const int b    = blockIdx.x;
    const int tid  = threadIdx.x;
    const int warp = tid >> 5;      // 0..7
    const int lane = tid & 31;

    // Load stat row into shared (coalesced, 2 per thread)
    s[tid]       = stat[(size_t)b * C_ + tid];
    s[tid + 256] = stat[(size_t)b * C_ + tid + 256];
    __syncthreads();

    // ---- Layer 1: 8 warps x 4 rows, lane-coalesced W1 loads ----
    {
        float acc[4];
#pragma unroll
        for (int j = 0; j < 4; ++j) {
            const int r = warp * 4 + j;
            const float* wr = W1 + (size_t)r * C_;
            float a = 0.0f;
#pragma unroll
            for (int k = 0; k < 16; ++k)
                a = fmaf(wr[lane + 32 * k], s[lane + 32 * k], a);
            acc[j] = a;
        }
#pragma unroll
        for (int j = 0; j < 4; ++j) {
            float a = acc[j];
#pragma unroll
            for (int o = 16; o > 0; o >>= 1)
                a += __shfl_xor_sync(0xFFFFFFFFu, a, o);
            if (lane == 0) h1[warp * 4 + j] = fmaxf(a + b1[warp * 4 + j], 0.0f);
        }
    }
    __syncthreads();

    // ---- Layers 2,3 + loss on warp 0 ----
    if (warp == 0) {
        const int t = lane;

        // Layer 2
        {
            float a = b2[t];
            const float* w = W2 + t * HID;
#pragma unroll
            for (int k = 0; k < HID; ++k) a = fmaf(w[k], h1[k], a);
            h2[t] = fmaxf(a, 0.0f);
        }
        __syncwarp();

        // Layer 3: 16 filter outputs
        if (t < 2 * FL) {
            float a = b3[t];
            const float* w = W3 + t * HID;
#pragma unroll
            for (int k = 0; k < HID; ++k) a = fmaf(w[k], h2[k], a);
            f[t] = a;
            if (t < FL) out[(size_t)b * FL + t] = a;                          // lo
            else        out[(size_t)B_ * FL + (size_t)b * FL + (t - FL)] = a; // hi
        }
        __syncwarp();

        // Per-sample ortho loss (lane 0)
        if (t == 0) {
            float lo[FL], hi[FL];
            float nl = 0.0f, nh = 0.0f;
#pragma unroll
            for (int i = 0; i < FL; ++i) {
                lo[i] = f[i]; hi[i] = f[FL + i];
                nl += lo[i] * lo[i];
                nh += hi[i] * hi[i];
            }
            const float il = 1.0f / sqrtf(nl);
            const float ih = 1.0f / sqrtf(nh);
            float Ln[FL], Hn[FL];
#pragma unroll
            for (int i = 0; i < FL; ++i) { Ln[i] = lo[i] * il; Hn[i] = hi[i] * ih; }

            float acc = 0.0f;
#pragma unroll
            for (int sft = 1; sft < FL; sft += 2) {   // shifts 1,3,5,7
                float d = 0.0f;
#pragma unroll
                for (int i = 0; i < FL; ++i) d += Ln[i] * Ln[(i - sft + FL) & (FL - 1)];
                acc += fabsf(d);
            }
            float dlh = 0.0f, dll = 0.0f, dhh = 0.0f;
#pragma unroll
            for (int i = 0; i < FL; ++i) {
                dlh += Ln[i] * Hn[i];
                dll += Ln[i] * Ln[i];
                dhh += Hn[i] * Hn[i];
            }
            acc += fabsf(dlh) + fabsf(dll - 1.0f) + fabsf(dhh - 1.0f);
            loss[b] = acc;
        }
    }
    __syncthreads();

    // ---- Fused final reduction: last of 256 blocks ----
    if (tid == 0) {
        __threadfence();                       // publish loss[b]  (256 total, cheap)
        s_final = (atomicAdd(&g_done_cnt, 1) == B_ - 1) ? 1 : 0;
    }
    __syncthreads();
    if (!s_final) return;

    if (tid == 0) g_done_cnt = 0;              // self-reset for graph replay

    if (tid < 32) {
        __threadfence();                       // acquire all loss writes
        float a = 0.0f;
#pragma unroll
        for (int i = 0; i < 8; ++i) a += loss[tid * 8 + i];
#pragma unroll
        for (int o = 16; o > 0; o >>= 1)
            a += __shfl_xor_sync(0xFFFFFFFFu, a, o);
        if (tid == 0) out[2 * B_ * FL] = a * (1.0f / (float)B_);
    }
}

// ---------------------------------------------------------------------------
extern "C" void kernel_launch(void* const* d_in, const int* in_sizes, int n_in,
                              void* d_out, int out_size)
{
    const float* x  = (const float*)d_in[0];
    const float* W1 = (const float*)d_in[1];
    const float* b1 = (const float*)d_in[2];
    const float* W2 = (const float*)d_in[3];
    const float* b2 = (const float*)d_in[4];
    const float* W3 = (const float*)d_in[5];
    const float* b3 = (const float*)d_in[6];
    float* out = (float*)d_out;

    float* stat;  cudaGetSymbolAddress((void**)&stat, g_stat);
    float* loss;  cudaGetSymbolAddress((void**)&loss, g_loss);

    dywan_max_kernel<<<(B_ * C_) / 8, 256>>>(x, stat);
    dywan_mlp_kernel<<<B_, 256>>>(stat, W1, b1, W2, b2, W3, b3, out, loss);
}

// round 13
// speedup vs baseline: 2.5218x; 1.0158x over previous
#include <cuda_runtime.h>
#include <math.h>

#define B_   256
#define C_   512
#define L_   2048
#define HID  32
#define FL   8

// Scratch (no allocations). Counter self-resets -> graph-replay safe.
__device__ float g_stat[B_ * C_];   // row maxes
__device__ float g_loss[B_];        // per-sample ortho loss
__device__ int   g_done_cnt;        // blocks of kernel B completed (0..256)

// ---------------------------------------------------------------------------
// Kernel A: stat[b,c] = max over L (proven shape: ~91% DRAM, ~148 us).
// Pure streaming; PDL trigger at top so kernel B can come resident early.
// ---------------------------------------------------------------------------
__global__ void __launch_bounds__(256) dywan_max_kernel(
    const float* __restrict__ x, float* __restrict__ stat)
{
#if __CUDA_ARCH__ >= 900
    cudaTriggerProgrammaticLaunchCompletion();
#endif
    const int warp = threadIdx.x >> 5;
    const int lane = threadIdx.x & 31;
    const int row  = blockIdx.x * 8 + warp;

    const float4* p = reinterpret_cast<const float4*>(x + (size_t)row * L_);
    float m = -INFINITY;
#pragma unroll
    for (int i = 0; i < 16; ++i) {
        float4 v = p[lane + 32 * i];
        m = fmaxf(m, fmaxf(fmaxf(v.x, v.y), fmaxf(v.z, v.w)));
    }
#pragma unroll
    for (int o = 16; o > 0; o >>= 1)
        m = fmaxf(m, __shfl_xor_sync(0xFFFFFFFFu, m, o));
    if (lane == 0) stat[row] = m;
}

// ---------------------------------------------------------------------------
// Kernel B: MLP + per-sample loss + fused final reduction, PDL secondary.
// Launches while A runs: prefetches W1 (64 KB) + small weights into shared,
// THEN waits on the grid dependency, so the post-A critical path is ~2us.
// 256 blocks x 256 threads; 256 fence/atomic pairs total (proven cheap).
// ---------------------------------------------------------------------------
__global__ void __launch_bounds__(256) dywan_mlp_kernel(
    const float* __restrict__ stat,
    const float* __restrict__ W1, const float* __restrict__ b1,
    const float* __restrict__ W2, const float* __restrict__ b2,
    const float* __restrict__ W3, const float* __restrict__ b3,
    float* __restrict__ out, float* __restrict__ loss)
{
    extern __shared__ float w1s[];        // [HID*C_] = 64 KB, dynamic
    __shared__ float s[C_];
    __shared__ float w2s[HID * HID];
    __shared__ float w3s[2 * FL * HID];
    __shared__ float b1s[HID], b2s[HID], b3s[2 * FL];
    __shared__ float h1[HID];
    __shared__ float h2[HID];
    __shared__ float f[2 * FL];
    __shared__ int   s_final;

    const int b    = blockIdx.x;
    const int tid  = threadIdx.x;
    const int warp = tid >> 5;            // 0..7
    const int lane = tid & 31;

    // ---- Prologue (overlaps kernel A): prefetch all weights into shared ----
    {
        // W1: 16384 floats = 4096 float4, 16 per thread (harness buffers are
        // 256B-aligned -> float4 on W1 is safe; shared dest is 16B-aligned).
        const float4* w1v = reinterpret_cast<const float4*>(W1);
        float4*       d1v = reinterpret_cast<float4*>(w1s);
#pragma unroll
        for (int i = 0; i < 16; ++i) d1v[tid + 256 * i] = w1v[tid + 256 * i];

        // W2 (1024), W3 (512), biases
        if (tid < HID * HID / 4) {
            reinterpret_cast<float4*>(w2s)[tid] =
                reinterpret_cast<const float4*>(W2)[tid];
        }
        if (tid < 2 * FL * HID / 4) {
            reinterpret_cast<float4*>(w3s)[tid] =
                reinterpret_cast<const float4*>(W3)[tid];
        }
        if (tid < HID)     b1s[tid] = b1[tid];
        else if (tid < 2 * HID)      b2s[tid - HID] = b2[tid - HID];
        else if (tid < 2 * HID + 2 * FL) b3s[tid - 2 * HID] = b3[tid - 2 * HID];
    }

    // ---- Wait for kernel A's stats to be visible ----
#if __CUDA_ARCH__ >= 900
    cudaGridDependencySynchronize();
#endif

    // Load stat row into shared (coalesced, 2 per thread)
    s[tid]       = stat[(size_t)b * C_ + tid];
    s[tid + 256] = stat[(size_t)b * C_ + tid + 256];
    __syncthreads();                      // also covers the weight prefetch

    // ---- Layer 1: 8 warps x 4 rows, conflict-free shared W1 ----
    {
        float acc[4];
#pragma unroll
        for (int j = 0; j < 4; ++j) {
            const int r = warp * 4 + j;
            const float* wr = w1s + r * C_;
            float a = 0.0f;
#pragma unroll
            for (int k = 0; k < 16; ++k)
                a = fmaf(wr[lane + 32 * k], s[lane + 32 * k], a);
            acc[j] = a;
        }
#pragma unroll
        for (int j = 0; j < 4; ++j) {
            float a = acc[j];
#pragma unroll
            for (int o = 16; o > 0; o >>= 1)
                a += __shfl_xor_sync(0xFFFFFFFFu, a, o);
            if (lane == 0) h1[warp * 4 + j] = fmaxf(a + b1s[warp * 4 + j], 0.0f);
        }
    }
    __syncthreads();

    // ---- Layers 2,3 + loss on warp 0 (all operands in shared) ----
    if (warp == 0) {
        const int t = lane;

        // Layer 2
        {
            float a = b2s[t];
            const float* w = w2s + t * HID;
#pragma unroll
            for (int k = 0; k < HID; ++k) a = fmaf(w[k], h1[k], a);
            h2[t] = fmaxf(a, 0.0f);
        }
        __syncwarp();

        // Layer 3: 16 filter outputs
        if (t < 2 * FL) {
            float a = b3s[t];
            const float* w = w3s + t * HID;
#pragma unroll
            for (int k = 0; k < HID; ++k) a = fmaf(w[k], h2[k], a);
            f[t] = a;
            if (t < FL) out[(size_t)b * FL + t] = a;                          // lo
            else        out[(size_t)B_ * FL + (size_t)b * FL + (t - FL)] = a; // hi
        }
        __syncwarp();

        // Per-sample ortho loss (lane 0)
        if (t == 0) {
            float lo[FL], hi[FL];
            float nl = 0.0f, nh = 0.0f;
#pragma unroll
            for (int i = 0; i < FL; ++i) {
                lo[i] = f[i]; hi[i] = f[FL + i];
                nl += lo[i] * lo[i];
                nh += hi[i] * hi[i];
            }
            const float il = 1.0f / sqrtf(nl);
            const float ih = 1.0f / sqrtf(nh);
            float Ln[FL], Hn[FL];
#pragma unroll
            for (int i = 0; i < FL; ++i) { Ln[i] = lo[i] * il; Hn[i] = hi[i] * ih; }

            float acc = 0.0f;
#pragma unroll
            for (int sft = 1; sft < FL; sft += 2) {   // shifts 1,3,5,7
                float d = 0.0f;
#pragma unroll
                for (int i = 0; i < FL; ++i) d += Ln[i] * Ln[(i - sft + FL) & (FL - 1)];
                acc += fabsf(d);
            }
            float dlh = 0.0f, dll = 0.0f, dhh = 0.0f;
#pragma unroll
            for (int i = 0; i < FL; ++i) {
                dlh += Ln[i] * Hn[i];
                dll += Ln[i] * Ln[i];
                dhh += Hn[i] * Hn[i];
            }
            acc += fabsf(dlh) + fabsf(dll - 1.0f) + fabsf(dhh - 1.0f);
            loss[b] = acc;
        }
    }
    __syncthreads();

    // ---- Fused final reduction: last of 256 blocks ----
    if (tid == 0) {
        __threadfence();                       // publish loss[b] (256 total, cheap)
        s_final = (atomicAdd(&g_done_cnt, 1) == B_ - 1) ? 1 : 0;
    }
    __syncthreads();
    if (!s_final) return;

    if (tid == 0) g_done_cnt = 0;              // self-reset for graph replay

    if (tid < 32) {
        __threadfence();                       // acquire all loss writes
        float a = 0.0f;
#pragma unroll
        for (int i = 0; i < 8; ++i) a += loss[tid * 8 + i];
#pragma unroll
        for (int o = 16; o > 0; o >>= 1)
            a += __shfl_xor_sync(0xFFFFFFFFu, a, o);
        if (tid == 0) out[2 * B_ * FL] = a * (1.0f / (float)B_);
    }
}

// ---------------------------------------------------------------------------
extern "C" void kernel_launch(void* const* d_in, const int* in_sizes, int n_in,
                              void* d_out, int out_size)
{
    const float* x  = (const float*)d_in[0];
    const float* W1 = (const float*)d_in[1];
    const float* b1 = (const float*)d_in[2];
    const float* W2 = (const float*)d_in[3];
    const float* b2 = (const float*)d_in[4];
    const float* W3 = (const float*)d_in[5];
    const float* b3 = (const float*)d_in[6];
    float* out = (float*)d_out;

    float* stat;  cudaGetSymbolAddress((void**)&stat, g_stat);
    float* loss;  cudaGetSymbolAddress((void**)&loss, g_loss);

    const int dyn_smem = HID * C_ * sizeof(float);   // 64 KB for W1
    static int attr_set = 0;
    if (!attr_set) {   // idempotent host-side attribute; not a stream op
        cudaFuncSetAttribute(dywan_mlp_kernel,
                             cudaFuncAttributeMaxDynamicSharedMemorySize, dyn_smem);
        attr_set = 1;
    }

    // Primary: streaming max kernel (PDL trigger at top of each block)
    dywan_max_kernel<<<(B_ * C_) / 8, 256>>>(x, stat);

    // Secondary: PDL launch — comes resident during A, prefetches weights,
    // then grid-dependency-syncs before consuming stats.
    cudaLaunchConfig_t cfg = {};
    cfg.gridDim  = dim3(B_, 1, 1);
    cfg.blockDim = dim3(256, 1, 1);
    cfg.dynamicSmemBytes = dyn_smem;
    cfg.stream = 0;
    cudaLaunchAttribute attrs[1];
    attrs[0].id = cudaLaunchAttributeProgrammaticStreamSerialization;
    attrs[0].val.programmaticStreamSerializationAllowed = 1;
    cfg.attrs = attrs;
    cfg.numAttrs = 1;
    cudaLaunchKernelEx(&cfg, dywan_mlp_kernel,
                       (const float*)stat, W1, b1, W2, b2, W3, b3, out, loss);
}

// round 15
// speedup vs baseline: 2.5244x; 1.0010x over previous
#include <cuda_runtime.h>
#include <math.h>

#define B_   256
#define C_   512
#define L_   2048
#define HID  32
#define FL   8

// Scratch (no allocations). Counters self-reset each run -> graph-replay safe.
__device__ float g_stat[B_ * C_];   // row maxes
__device__ float g_loss[B_];        // per-sample ortho loss
__device__ int   g_samp_cnt[B_];    // blocks completed per sample (0..64)
__device__ int   g_done_cnt;        // samples completed (0..256)

// acq_rel device-scope fetch-add: release publishes this block's prior stores
// (combined with __syncthreads' block-level happens-before); acquire on the
// winning observation makes all peers' released stores visible. Crucially this
// does NOT emit the CCTL.IVALL L1-flush that __threadfence() does -- that
// flush, executed 16384x, was the R8 catastrophe.
__device__ __forceinline__ int atom_add_acq_rel(int* p, int v) {
    int old;
    asm volatile("atom.acq_rel.gpu.add.s32 %0, [%1], %2;"
                 : "=r"(old) : "l"(p), "r"(v) : "memory");
    return old;
}

// ---------------------------------------------------------------------------
// Single fused kernel. Proven streaming shape: 16384 blocks x 256 threads,
// one warp per row (2048 floats, float4), 110 self-balancing waves.
// The 64th block of each sample runs that sample's MLP with all 8 warps;
// the 256th sample-completer does the final deterministic loss reduction.
// ---------------------------------------------------------------------------
__global__ void __launch_bounds__(256) dywan_fused_kernel(
    const float* __restrict__ x,
    const float* __restrict__ W1, const float* __restrict__ b1,
    const float* __restrict__ W2, const float* __restrict__ b2,
    const float* __restrict__ W3, const float* __restrict__ b3,
    float* __restrict__ out)
{
    __shared__ float s[C_];
    __shared__ float h1[HID];
    __shared__ float h2[HID];
    __shared__ float f[2 * FL];
    __shared__ int   s_last;
    __shared__ int   s_final;

    const int warp = threadIdx.x >> 5;
    const int lane = threadIdx.x & 31;
    const int tid  = threadIdx.x;
    const int row  = blockIdx.x * 8 + warp;
    const int b    = blockIdx.x >> 6;          // 64 blocks per sample

    // ---- Phase 1: row max (pure streaming, identical to proven 91.8% path) ----
    {
        const float4* p = reinterpret_cast<const float4*>(x + (size_t)row * L_);
        float m = -INFINITY;
#pragma unroll
        for (int i = 0; i < 16; ++i) {
            float4 v = p[lane + 32 * i];
            m = fmaxf(m, fmaxf(fmaxf(v.x, v.y), fmaxf(v.z, v.w)));
        }
#pragma unroll
        for (int o = 16; o > 0; o >>= 1)
            m = fmaxf(m, __shfl_xor_sync(0xFFFFFFFFu, m, o));
        if (lane == 0) g_stat[row] = m;
    }
    __syncthreads();                 // block's 8 stat writes happen-before tid 0

    // ---- Cheap release+count: ONE acq_rel ATOMG per block, no fences ----
    if (tid == 0)
        s_last = (atom_add_acq_rel(&g_samp_cnt[b], 1) == 63) ? 1 : 0;
    __syncthreads();
    if (!s_last) return;             // 63 of 64 blocks exit here

    // ---- Phase 2: winning block runs sample b's MLP with all 8 warps ----
    if (tid == 0) g_samp_cnt[b] = 0; // self-reset (no racers remain)

    // stats into shared (coalesced, 2 per thread); acquire above makes visible
    s[tid]       = g_stat[(size_t)b * C_ + tid];
    s[tid + 256] = g_stat[(size_t)b * C_ + tid + 256];
    __syncthreads();

    // Layer 1: 8 warps x 4 rows, lane-coalesced W1 loads (L2-hot from prior winners)
    {
        float acc[4];
#pragma unroll
        for (int j = 0; j < 4; ++j) {
            const int r = warp * 4 + j;
            const float* wr = W1 + (size_t)r * C_;
            float a = 0.0f;
#pragma unroll
            for (int k = 0; k < 16; ++k)
                a = fmaf(wr[lane + 32 * k], s[lane + 32 * k], a);
            acc[j] = a;
        }
#pragma unroll
        for (int j = 0; j < 4; ++j) {
            float a = acc[j];
#pragma unroll
            for (int o = 16; o > 0; o >>= 1)
                a += __shfl_xor_sync(0xFFFFFFFFu, a, o);
            if (lane == 0) h1[warp * 4 + j] = fmaxf(a + b1[warp * 4 + j], 0.0f);
        }
    }
    __syncthreads();

    // Layers 2,3 + per-sample loss on warp 0
    if (warp == 0) {
        const int t = lane;

        // Layer 2
        {
            float a = b2[t];
            const float* w = W2 + t * HID;
#pragma unroll
            for (int k = 0; k < HID; ++k) a = fmaf(w[k], h1[k], a);
            h2[t] = fmaxf(a, 0.0f);
        }
        __syncwarp();

        // Layer 3: 16 filter outputs
        if (t < 2 * FL) {
            float a = b3[t];
            const float* w = W3 + t * HID;
#pragma unroll
            for (int k = 0; k < HID; ++k) a = fmaf(w[k], h2[k], a);
            f[t] = a;
            if (t < FL) out[(size_t)b * FL + t] = a;                          // lo
            else        out[(size_t)B_ * FL + (size_t)b * FL + (t - FL)] = a; // hi
        }
        __syncwarp();

        // Per-sample ortho loss (lane 0) -> g_loss[b]
        if (t == 0) {
            float lo[FL], hi[FL];
            float nl = 0.0f, nh = 0.0f;
#pragma unroll
            for (int i = 0; i < FL; ++i) {
                lo[i] = f[i]; hi[i] = f[FL + i];
                nl += lo[i] * lo[i];
                nh += hi[i] * hi[i];
            }
            const float il = 1.0f / sqrtf(nl);
            const float ih = 1.0f / sqrtf(nh);
            float Ln[FL], Hn[FL];
#pragma unroll
            for (int i = 0; i < FL; ++i) { Ln[i] = lo[i] * il; Hn[i] = hi[i] * ih; }

            float acc = 0.0f;
#pragma unroll
            for (int sft = 1; sft < FL; sft += 2) {   // shifts 1,3,5,7
                float d = 0.0f;
#pragma unroll
                for (int i = 0; i < FL; ++i) d += Ln[i] * Ln[(i - sft + FL) & (FL - 1)];
                acc += fabsf(d);
            }
            float dlh = 0.0f, dll = 0.0f, dhh = 0.0f;
#pragma unroll
            for (int i = 0; i < FL; ++i) {
                dlh += Ln[i] * Hn[i];
                dll += Ln[i] * Ln[i];
                dhh += Hn[i] * Hn[i];
            }
            acc += fabsf(dlh) + fabsf(dll - 1.0f) + fabsf(dhh - 1.0f);
            g_loss[b] = acc;
        }
    }
    __syncthreads();                 // g_loss[b] happens-before tid 0's atomic

    // ---- Phase 3: last sample overall reduces the 256 losses ----
    if (tid == 0)
        s_final = (atom_add_acq_rel(&g_done_cnt, 1) == B_ - 1) ? 1 : 0;
    __syncthreads();
    if (!s_final) return;

    if (tid == 0) g_done_cnt = 0;    // self-reset for graph replay

    if (tid < 32) {
        // deterministic: fixed per-lane serial sum then fixed shuffle tree
        float a = 0.0f;
#pragma unroll
        for (int i = 0; i < 8; ++i) a += g_loss[tid * 8 + i];
#pragma unroll
        for (int o = 16; o > 0; o >>= 1)
            a += __shfl_xor_sync(0xFFFFFFFFu, a, o);
        if (tid == 0) out[2 * B_ * FL] = a * (1.0f / (float)B_);
    }
}

// ---------------------------------------------------------------------------
extern "C" void kernel_launch(void* const* d_in, const int* in_sizes, int n_in,
                              void* d_out, int out_size)
{
    const float* x  = (const float*)d_in[0];
    const float* W1 = (const float*)d_in[1];
    const float* b1 = (const float*)d_in[2];
    const float* W2 = (const float*)d_in[3];
    const float* b2 = (const float*)d_in[4];
    const float* W3 = (const float*)d_in[5];
    const float* b3 = (const float*)d_in[6];
    float* out = (float*)d_out;

    dywan_fused_kernel<<<(B_ * C_) / 8, 256>>>(x, W1, b1, W2, b2, W3, b3, out);
}